// round 5
// baseline (speedup 1.0000x reference)
#include <cuda_runtime.h>
#include <cuda_bf16.h>
#include <cstdint>
#include <math.h>

#define NROWS 65536
#define DD    512
#define KSPLIT 64
#define KCHUNK (NROWS / KSPLIT)   // 1024
#define NS_ITERS 10
#define INV_TEMP 0.1f

// ---------------------------------------------------------------------------
// Static device scratch
// ---------------------------------------------------------------------------
__device__ float g_covp[(size_t)KSPLIT * DD * DD];   // 64 MB
__device__ float g_G[DD * DD];
__device__ float g_S[DD * DD];
__device__ float g_P[DD * DD];
__device__ float g_Pn[DD * DD];
__device__ float g_colp[512 * DD];                   // per-rowblock column sums
__device__ float g_mean[DD];
__device__ float g_mc[DD];
__device__ float g_scalars[4];
__device__ __nv_bfloat16 g_Ah[(size_t)NROWS * DD];
__device__ __nv_bfloat16 g_Al[(size_t)NROWS * DD];
__device__ __nv_bfloat16 g_Hh[(size_t)NROWS * DD];
__device__ __nv_bfloat16 g_Hl[(size_t)NROWS * DD];
__device__ __nv_bfloat16 g_Wh[DD * DD];
__device__ __nv_bfloat16 g_Wl[DD * DD];
__device__ __nv_bfloat16 g_Sh[DD * DD], g_Sl[DD * DD];
__device__ __nv_bfloat16 g_Pah[DD * DD], g_Pal[DD * DD];
__device__ __nv_bfloat16 g_Pbh[DD * DD], g_Pbl[DD * DD];
__device__ __nv_bfloat16 g_T1h[DD * DD], g_T1l[DD * DD];
__device__ __nv_bfloat16 g_T2h[DD * DD], g_T2l[DD * DD];

// ---------------------------------------------------------------------------
// PTX helpers
// ---------------------------------------------------------------------------
__device__ __forceinline__ uint32_t smem_u32(const void* p) {
    uint32_t a;
    asm("{ .reg .u64 t; cvta.to.shared.u64 t, %1; cvt.u32.u64 %0, t; }"
        : "=r"(a) : "l"(p));
    return a;
}
__device__ __forceinline__ void cpa16(uint32_t dst, const void* src) {
    asm volatile("cp.async.cg.shared.global [%0], [%1], 16;"
                 :: "r"(dst), "l"(src) : "memory");
}
#define CP_COMMIT() asm volatile("cp.async.commit_group;" ::: "memory")
#define CP_WAIT0()  asm volatile("cp.async.wait_group 0;" ::: "memory")
#define CP_WAIT1()  asm volatile("cp.async.wait_group 1;" ::: "memory")

__device__ __forceinline__ void ldsm4(uint32_t* r, uint32_t a) {
    asm volatile("ldmatrix.sync.aligned.m8n8.x4.shared.b16 {%0,%1,%2,%3}, [%4];"
        : "=r"(r[0]), "=r"(r[1]), "=r"(r[2]), "=r"(r[3]) : "r"(a));
}
__device__ __forceinline__ void ldsm4t(uint32_t* r, uint32_t a) {
    asm volatile("ldmatrix.sync.aligned.m8n8.x4.trans.shared.b16 {%0,%1,%2,%3}, [%4];"
        : "=r"(r[0]), "=r"(r[1]), "=r"(r[2]), "=r"(r[3]) : "r"(a));
}
__device__ __forceinline__ void mma_bf16(float* d, const uint32_t* a, const uint32_t* b) {
    asm volatile("mma.sync.aligned.m16n8k16.row.col.f32.bf16.bf16.f32 "
        "{%0,%1,%2,%3}, {%4,%5,%6,%7}, {%8,%9}, {%0,%1,%2,%3};"
        : "+f"(d[0]), "+f"(d[1]), "+f"(d[2]), "+f"(d[3])
        : "r"(a[0]), "r"(a[1]), "r"(a[2]), "r"(a[3]), "r"(b[0]), "r"(b[1]));
}

__device__ __forceinline__ void split1(float v, __nv_bfloat16& h, __nv_bfloat16& l) {
    h = __float2bfloat16_rn(v);
    l = __float2bfloat16_rn(v - __bfloat162float(h));
}
__device__ __forceinline__ void store_split1(__nv_bfloat16* Xh, __nv_bfloat16* Xl,
                                             size_t off, float v) {
    split1(v, Xh[off], Xl[off]);
}
__device__ __forceinline__ void store_split2(__nv_bfloat16* Xh, __nv_bfloat16* Xl,
                                             size_t off, float a, float b) {
    __nv_bfloat16 ha, la, hb, lb;
    split1(a, ha, la);
    split1(b, hb, lb);
    *(uint32_t*)(Xh + off) =
        ((uint32_t)__bfloat16_as_ushort(hb) << 16) | __bfloat16_as_ushort(ha);
    *(uint32_t*)(Xl + off) =
        ((uint32_t)__bfloat16_as_ushort(lb) << 16) | __bfloat16_as_ushort(la);
}

__global__ void split_f32(const float* __restrict__ X,
                          __nv_bfloat16* __restrict__ Xh, __nv_bfloat16* __restrict__ Xl)
{
    const size_t i = ((size_t)blockIdx.x * blockDim.x + threadIdx.x) * 4;
    float4 v = *(const float4*)(X + i);
    __nv_bfloat16 h[4], l[4];
    split1(v.x, h[0], l[0]); split1(v.y, h[1], l[1]);
    split1(v.z, h[2], l[2]); split1(v.w, h[3], l[3]);
    *(uint64_t*)(Xh + i) = *(const uint64_t*)h;
    *(uint64_t*)(Xl + i) = *(const uint64_t*)l;
}

// ---------------------------------------------------------------------------
// Big GEMM via mma.sync: C[M,512] = A @ B (bf16 3-term emulation)
// 3-stage cp.async pipeline.
// MODE 0: write split(acc) to Ch/Cl + per-rowblock column sums into colp.
// MODE 1: write fp32 acc*s2 - mc[col] to Cf32 AND split of it to Ch/Cl.
// ---------------------------------------------------------------------------
#define LDA 80
#define LDB 272
#define A_TILE (128 * LDA)
#define B_TILE (32 * LDB)
#define G1_STAGE (2 * A_TILE + 2 * B_TILE)   // 37888
#define G1_SMEM (3 * G1_STAGE)               // 113664

template<int MODE>
__global__ void __launch_bounds__(256)
hgemm(const __nv_bfloat16* __restrict__ Ah, const __nv_bfloat16* __restrict__ Al,
      const __nv_bfloat16* __restrict__ Bh, const __nv_bfloat16* __restrict__ Bl,
      float* __restrict__ Cf32,
      __nv_bfloat16* __restrict__ Ch, __nv_bfloat16* __restrict__ Cl,
      const float* __restrict__ scalars, const float* __restrict__ mc,
      float* __restrict__ colp)
{
    extern __shared__ __align__(16) char smem[];
    const uint32_t sb = smem_u32(smem);
    const int tid = threadIdx.x;
    const int lane = tid & 31;
    const int wid = tid >> 5;
    const int m0 = blockIdx.y * 128;
    const int n0 = blockIdx.x * 128;
    const int wm = (wid & 1) * 64;
    const int wn = (wid >> 1) * 32;

    float acc[4][4][4] = {};

    auto loadStage = [&](int c, int s) {
        const uint32_t base = sb + s * G1_STAGE;
        const int k0 = c * 32;
#pragma unroll
        for (int rep = 0; rep < 4; rep++) {
            const int idx = rep * 256 + tid;
            const int half = idx >> 9, r = (idx >> 2) & 127, ch = idx & 3;
            const __nv_bfloat16* src =
                (half ? Al : Ah) + (size_t)(m0 + r) * DD + k0 + ch * 8;
            cpa16(base + half * A_TILE + r * LDA + ch * 16, src);
        }
#pragma unroll
        for (int rep = 0; rep < 4; rep++) {
            const int idx = rep * 256 + tid;
            const int half = idx >> 9, r = (idx >> 4) & 31, ch = idx & 15;
            const __nv_bfloat16* src =
                (half ? Bl : Bh) + (size_t)(k0 + r) * DD + n0 + ch * 8;
            cpa16(base + 2 * A_TILE + half * B_TILE + r * LDB + ch * 16, src);
        }
        CP_COMMIT();
    };

    const int NC = DD / 32;    // 16
    loadStage(0, 0);
    loadStage(1, 1);
    int sidx = 0;              // stage of chunk c
    int lidx = 2;              // stage for chunk c+2

    for (int c = 0; c < NC; c++) {
        if (c == NC - 1) CP_WAIT0(); else CP_WAIT1();
        __syncthreads();
        const uint32_t st = sb + sidx * G1_STAGE;

#pragma unroll
        for (int ks = 0; ks < 2; ks++) {
            uint32_t ah[4][4], al[4][4];
            const uint32_t abase = st + (lane & 15) * LDA + ks * 32 + (lane >> 4) * 16;
#pragma unroll
            for (int mt = 0; mt < 4; mt++) {
                ldsm4(ah[mt], abase + (wm + mt * 16) * LDA);
                ldsm4(al[mt], abase + A_TILE + (wm + mt * 16) * LDA);
            }
            const uint32_t brow = ks * 16 + (lane & 7) + ((lane >> 3) & 1) * 8;
            const uint32_t bbase = st + 2 * A_TILE + brow * LDB + wn * 2 + (lane >> 4) * 16;
            uint32_t bh[2][4], bl[2][4];
            ldsm4t(bh[0], bbase);
            ldsm4t(bh[1], bbase + 32);
            ldsm4t(bl[0], bbase + B_TILE);
            ldsm4t(bl[1], bbase + B_TILE + 32);

#pragma unroll
            for (int mt = 0; mt < 4; mt++)
#pragma unroll
                for (int nt = 0; nt < 4; nt++) {
                    const uint32_t* ph = &bh[nt >> 1][(nt & 1) * 2];
                    const uint32_t* pl = &bl[nt >> 1][(nt & 1) * 2];
                    mma_bf16(acc[mt][nt], ah[mt], ph);
                    mma_bf16(acc[mt][nt], ah[mt], pl);
                    mma_bf16(acc[mt][nt], al[mt], ph);
                }
        }

        if (c + 2 < NC) loadStage(c + 2, lidx);
        sidx = (sidx == 2) ? 0 : sidx + 1;
        lidx = (lidx == 2) ? 0 : lidx + 1;
    }

    const float s2 = (MODE == 1) ? scalars[2] : 1.0f;
    const int g = lane >> 2, t4 = lane & 3;
#pragma unroll
    for (int mt = 0; mt < 4; mt++) {
        const int r0 = m0 + wm + mt * 16 + g;
#pragma unroll
        for (int nt = 0; nt < 4; nt++) {
            const int cc = n0 + wn + nt * 8 + 2 * t4;
            float v0 = acc[mt][nt][0], v1 = acc[mt][nt][1];
            float v2 = acc[mt][nt][2], v3 = acc[mt][nt][3];
            if (MODE == 1) {
                const float2 m2 = *(const float2*)&mc[cc];
                v0 = v0 * s2 - m2.x; v1 = v1 * s2 - m2.y;
                v2 = v2 * s2 - m2.x; v3 = v3 * s2 - m2.y;
                *(float2*)&Cf32[(size_t)r0 * DD + cc] = make_float2(v0, v1);
                *(float2*)&Cf32[(size_t)(r0 + 8) * DD + cc] = make_float2(v2, v3);
            }
            store_split2(Ch, Cl, (size_t)r0 * DD + cc, v0, v1);
            store_split2(Ch, Cl, (size_t)(r0 + 8) * DD + cc, v2, v3);
        }
    }

    if (MODE == 0) {
        // fused column sums over this block's 128 rows (deterministic)
        float cs[4][2];
#pragma unroll
        for (int nt = 0; nt < 4; nt++) {
            cs[nt][0] = 0.0f; cs[nt][1] = 0.0f;
#pragma unroll
            for (int mt = 0; mt < 4; mt++) {
                cs[nt][0] += acc[mt][nt][0] + acc[mt][nt][2];
                cs[nt][1] += acc[mt][nt][1] + acc[mt][nt][3];
            }
        }
#pragma unroll
        for (int off = 4; off <= 16; off <<= 1)
#pragma unroll
            for (int nt = 0; nt < 4; nt++) {
                cs[nt][0] += __shfl_xor_sync(0xffffffffu, cs[nt][0], off);
                cs[nt][1] += __shfl_xor_sync(0xffffffffu, cs[nt][1], off);
            }
        float* smcs = (float*)smem;
        __syncthreads();
        if ((wid & 1) == 0 && g == 0) {
#pragma unroll
            for (int nt = 0; nt < 4; nt++) {
                const int c0 = wn + nt * 8 + 2 * t4;
                smcs[c0] = cs[nt][0];
                smcs[c0 + 1] = cs[nt][1];
            }
        }
        __syncthreads();
        if ((wid & 1) == 1 && g == 0) {
#pragma unroll
            for (int nt = 0; nt < 4; nt++) {
                const int c0 = wn + nt * 8 + 2 * t4;
                colp[(size_t)blockIdx.y * DD + n0 + c0] = smcs[c0] + cs[nt][0];
                colp[(size_t)blockIdx.y * DD + n0 + c0 + 1] = smcs[c0 + 1] + cs[nt][1];
            }
        }
    }
}

// ---------------------------------------------------------------------------
// Covariance split-K (upper-triangle tiles): Cp[z] = Hc^T Hc, 3-stage pipeline
// ---------------------------------------------------------------------------
#define CV_STAGE (4 * B_TILE)      // 34816
#define CV_SMEM (3 * CV_STAGE)     // 104448

__global__ void __launch_bounds__(256)
hcov(const __nv_bfloat16* __restrict__ Hh, const __nv_bfloat16* __restrict__ Hl,
     float* __restrict__ Cp)
{
    extern __shared__ __align__(16) char smem[];
    const uint32_t sb = smem_u32(smem);
    const int tid = threadIdx.x;
    const int lane = tid & 31;
    const int wid = tid >> 5;
    const int bx = blockIdx.x;
    const int bi = (bx < 4) ? 0 : (bx < 7) ? 1 : (bx < 9) ? 2 : 3;
    const int bj = bx - ((bi == 0) ? 0 : (bi == 1) ? 3 : (bi == 2) ? 5 : 6);
    const int i0 = bi * 128;
    const int j0 = bj * 128;
    const int z  = blockIdx.z;
    const int wm = (wid & 1) * 64;
    const int wn = (wid >> 1) * 32;

    float acc[4][4][4] = {};

    auto loadStage = [&](int c, int s) {
        const uint32_t base = sb + s * CV_STAGE;
        const int nbase = z * KCHUNK + c * 32;
#pragma unroll
        for (int rep = 0; rep < 8; rep++) {
            const int idx = rep * 256 + tid;
            const int tile = idx >> 9;
            const int r = (idx >> 4) & 31, ch = idx & 15;
            const __nv_bfloat16* basep = (tile & 1) ? Hl : Hh;
            const int coff = (tile < 2) ? i0 : j0;
            const __nv_bfloat16* src = basep + (size_t)(nbase + r) * DD + coff + ch * 8;
            cpa16(base + tile * B_TILE + r * LDB + ch * 16, src);
        }
        CP_COMMIT();
    };

    const int NC = KCHUNK / 32;   // 32
    loadStage(0, 0);
    loadStage(1, 1);
    int sidx = 0, lidx = 2;

    for (int c = 0; c < NC; c++) {
        if (c == NC - 1) CP_WAIT0(); else CP_WAIT1();
        __syncthreads();
        const uint32_t st = sb + sidx * CV_STAGE;

#pragma unroll
        for (int ks = 0; ks < 2; ks++) {
            const uint32_t arow = ks * 16 + (lane & 7) + ((lane >> 4) & 1) * 8;
            const uint32_t abase = st + arow * LDB + wm * 2 + ((lane >> 3) & 1) * 16;
            uint32_t ah[4][4], al[4][4];
#pragma unroll
            for (int mt = 0; mt < 4; mt++) {
                ldsm4t(ah[mt], abase + mt * 32);
                ldsm4t(al[mt], abase + B_TILE + mt * 32);
            }
            const uint32_t brow = ks * 16 + (lane & 7) + ((lane >> 3) & 1) * 8;
            const uint32_t bbase = st + 2 * B_TILE + brow * LDB + wn * 2 + (lane >> 4) * 16;
            uint32_t bh[2][4], bl[2][4];
            ldsm4t(bh[0], bbase);
            ldsm4t(bh[1], bbase + 32);
            ldsm4t(bl[0], bbase + B_TILE);
            ldsm4t(bl[1], bbase + B_TILE + 32);

#pragma unroll
            for (int mt = 0; mt < 4; mt++)
#pragma unroll
                for (int nt = 0; nt < 4; nt++) {
                    const uint32_t* ph = &bh[nt >> 1][(nt & 1) * 2];
                    const uint32_t* pl = &bl[nt >> 1][(nt & 1) * 2];
                    mma_bf16(acc[mt][nt], ah[mt], ph);
                    mma_bf16(acc[mt][nt], ah[mt], pl);
                    mma_bf16(acc[mt][nt], al[mt], ph);
                }
        }

        if (c + 2 < NC) loadStage(c + 2, lidx);
        sidx = (sidx == 2) ? 0 : sidx + 1;
        lidx = (lidx == 2) ? 0 : lidx + 1;
    }

    float* out = Cp + (size_t)z * DD * DD;
    const int g = lane >> 2, t4 = lane & 3;
#pragma unroll
    for (int mt = 0; mt < 4; mt++) {
        const int r0 = i0 + wm + mt * 16 + g;
#pragma unroll
        for (int nt = 0; nt < 4; nt++) {
            const int cc = j0 + wn + nt * 8 + 2 * t4;
            float2 v0 = {acc[mt][nt][0], acc[mt][nt][1]};
            float2 v1 = {acc[mt][nt][2], acc[mt][nt][3]};
            *(float2*)&out[(size_t)r0 * DD + cc] = v0;
            *(float2*)&out[(size_t)(r0 + 8) * DD + cc] = v1;
        }
    }
}

__global__ void reduce_cov_sym(const float* __restrict__ Cp, float* __restrict__ G)
{
    const int i = blockIdx.x, j = threadIdx.x;
    if (j < i) return;
    float s = 0.0f;
#pragma unroll 8
    for (int zz = 0; zz < KSPLIT; zz++)
        s += Cp[(size_t)zz * DD * DD + i * DD + j];
    G[i * DD + j] = s;
    G[j * DD + i] = s;
}

// ---------------------------------------------------------------------------
// Newton-Schulz small GEMMs (tensor cores, symmetric upper-triangle tiles)
// ---------------------------------------------------------------------------
#define NS_LDA 80
#define NS_AT  (64 * NS_LDA)
#define NS_LDB 144
#define NS_BT  (32 * NS_LDB)
#define NS_STAGE (2 * NS_AT + 2 * NS_BT)
#define NS_SMEM  (2 * NS_STAGE)

struct NsAcc { float a[2][4][4]; };

__device__ __forceinline__ void ns_tri(int bx, int& ti, int& tj) {
    int t = 0, rem = bx;
    while (rem >= 8 - t) { rem -= 8 - t; t++; }
    ti = t; tj = t + rem;
}

__device__ __forceinline__ void ns_core(
    const __nv_bfloat16* __restrict__ Ah, const __nv_bfloat16* __restrict__ Al,
    const __nv_bfloat16* __restrict__ Bh, const __nv_bfloat16* __restrict__ Bl,
    int m0, int n0, uint32_t sb, NsAcc& A)
{
    const int tid = threadIdx.x;
    const int lane = tid & 31;
    const int wid = tid >> 5;
    const int wm = (wid & 1) * 32;
    const int wn = (wid >> 1) * 32;

    auto loadStage = [&](int c, int s) {
        const uint32_t base = sb + s * NS_STAGE;
        const int k0 = c * 32;
#pragma unroll
        for (int rep = 0; rep < 8; rep++) {
            const int idx = rep * 128 + tid;
            if (idx < 512) {
                const int half = idx >> 8, r = (idx >> 2) & 63, ch = idx & 3;
                const __nv_bfloat16* src =
                    (half ? Al : Ah) + (size_t)(m0 + r) * DD + k0 + ch * 8;
                cpa16(base + half * NS_AT + r * NS_LDA + ch * 16, src);
            } else {
                const int j = idx - 512;
                const int half = j >> 8, r = (j >> 3) & 31, ch = j & 7;
                const __nv_bfloat16* src =
                    (half ? Bl : Bh) + (size_t)(k0 + r) * DD + n0 + ch * 8;
                cpa16(base + 2 * NS_AT + half * NS_BT + r * NS_LDB + ch * 16, src);
            }
        }
        CP_COMMIT();
    };

    loadStage(0, 0);

    for (int c = 0; c < DD / 32; c++) {
        CP_WAIT0();
        __syncthreads();
        if (c + 1 < DD / 32) loadStage(c + 1, (c + 1) & 1);
        const uint32_t st = sb + (c & 1) * NS_STAGE;

#pragma unroll
        for (int ks = 0; ks < 2; ks++) {
            uint32_t ah[2][4], al[2][4];
            const uint32_t abase = st + (lane & 15) * NS_LDA + ks * 32 + (lane >> 4) * 16;
#pragma unroll
            for (int mt = 0; mt < 2; mt++) {
                ldsm4(ah[mt], abase + (wm + mt * 16) * NS_LDA);
                ldsm4(al[mt], abase + NS_AT + (wm + mt * 16) * NS_LDA);
            }
            const uint32_t brow = ks * 16 + (lane & 7) + ((lane >> 3) & 1) * 8;
            const uint32_t bbase = st + 2 * NS_AT + brow * NS_LDB + wn * 2 + (lane >> 4) * 16;
            uint32_t bh[2][4], bl[2][4];
            ldsm4t(bh[0], bbase);
            ldsm4t(bh[1], bbase + 32);
            ldsm4t(bl[0], bbase + NS_BT);
            ldsm4t(bl[1], bbase + NS_BT + 32);

#pragma unroll
            for (int mt = 0; mt < 2; mt++)
#pragma unroll
                for (int nt = 0; nt < 4; nt++) {
                    const uint32_t* ph = &bh[nt >> 1][(nt & 1) * 2];
                    const uint32_t* pl = &bl[nt >> 1][(nt & 1) * 2];
                    mma_bf16(A.a[mt][nt], ah[mt], ph);
                    mma_bf16(A.a[mt][nt], ah[mt], pl);
                    mma_bf16(A.a[mt][nt], al[mt], ph);
                }
        }
    }
}

// grid (36,1,2): z=0 -> T1 = P @ S ; z=1 -> T2 = P @ P ; symmetric, mirrored
__global__ void __launch_bounds__(128)
ns_pair(const __nv_bfloat16* __restrict__ Pah, const __nv_bfloat16* __restrict__ Pal,
        const __nv_bfloat16* __restrict__ Sh,  const __nv_bfloat16* __restrict__ Sl,
        __nv_bfloat16* __restrict__ T1h, __nv_bfloat16* __restrict__ T1l,
        __nv_bfloat16* __restrict__ T2h, __nv_bfloat16* __restrict__ T2l)
{
    __shared__ __align__(16) char smem[NS_SMEM];
    const uint32_t sb = smem_u32(smem);
    int ti, tj;
    ns_tri(blockIdx.x, ti, tj);
    const int m0 = ti * 64;
    const int n0 = tj * 64;
    const int lane = threadIdx.x & 31;
    const int wid = threadIdx.x >> 5;
    const int wm = (wid & 1) * 32;
    const int wn = (wid >> 1) * 32;

    NsAcc A = {};
    const __nv_bfloat16* Bh = blockIdx.z ? Pah : Sh;
    const __nv_bfloat16* Bl = blockIdx.z ? Pal : Sl;
    ns_core(Pah, Pal, Bh, Bl, m0, n0, sb, A);

    __nv_bfloat16* Oh = blockIdx.z ? T2h : T1h;
    __nv_bfloat16* Ol = blockIdx.z ? T2l : T1l;
    const int g = lane >> 2, t4 = lane & 3;
    const bool mir = (ti != tj);
#pragma unroll
    for (int mt = 0; mt < 2; mt++) {
        const int r0 = m0 + wm + mt * 16 + g;
#pragma unroll
        for (int nt = 0; nt < 4; nt++) {
            const int cc = n0 + wn + nt * 8 + 2 * t4;
            const float v0 = A.a[mt][nt][0], v1 = A.a[mt][nt][1];
            const float v2 = A.a[mt][nt][2], v3 = A.a[mt][nt][3];
            store_split2(Oh, Ol, (size_t)r0 * DD + cc, v0, v1);
            store_split2(Oh, Ol, (size_t)(r0 + 8) * DD + cc, v2, v3);
            if (mir) {
                store_split1(Oh, Ol, (size_t)cc * DD + r0, v0);
                store_split1(Oh, Ol, (size_t)(cc + 1) * DD + r0, v1);
                store_split1(Oh, Ol, (size_t)cc * DD + r0 + 8, v2);
                store_split1(Oh, Ol, (size_t)(cc + 1) * DD + r0 + 8, v3);
            }
        }
    }
}

// grid (36): Pb = 1.5*Pold - 0.5*(T2 @ T1); symmetric, mirrored; fp32 + splits
__global__ void __launch_bounds__(128)
ns_update(const __nv_bfloat16* __restrict__ T2h, const __nv_bfloat16* __restrict__ T2l,
          const __nv_bfloat16* __restrict__ T1h, const __nv_bfloat16* __restrict__ T1l,
          const float* __restrict__ Pold, float* __restrict__ Pnew,
          __nv_bfloat16* __restrict__ Pnh, __nv_bfloat16* __restrict__ Pnl)
{
    __shared__ __align__(16) char smem[NS_SMEM];
    const uint32_t sb = smem_u32(smem);
    int ti, tj;
    ns_tri(blockIdx.x, ti, tj);
    const int m0 = ti * 64;
    const int n0 = tj * 64;
    const int lane = threadIdx.x & 31;
    const int wid = threadIdx.x >> 5;
    const int wm = (wid & 1) * 32;
    const int wn = (wid >> 1) * 32;

    NsAcc A = {};
    ns_core(T2h, T2l, T1h, T1l, m0, n0, sb, A);

    const int g = lane >> 2, t4 = lane & 3;
    const bool mir = (ti != tj);
#pragma unroll
    for (int mt = 0; mt < 2; mt++) {
        const int r0 = m0 + wm + mt * 16 + g;
#pragma unroll
        for (int nt = 0; nt < 4; nt++) {
            const int cc = n0 + wn + nt * 8 + 2 * t4;
#pragma unroll
            for (int half = 0; half < 2; half++) {
                const int r = r0 + half * 8;
                const size_t idx = (size_t)r * DD + cc;
                const float2 po = *(const float2*)&Pold[idx];
                const float v0 = 1.5f * po.x - 0.5f * A.a[mt][nt][half * 2 + 0];
                const float v1 = 1.5f * po.y - 0.5f * A.a[mt][nt][half * 2 + 1];
                *(float2*)&Pnew[idx] = make_float2(v0, v1);
                store_split2(Pnh, Pnl, idx, v0, v1);
                if (mir) {
                    Pnew[(size_t)cc * DD + r] = v0;
                    Pnew[(size_t)(cc + 1) * DD + r] = v1;
                    store_split1(Pnh, Pnl, (size_t)cc * DD + r, v0);
                    store_split1(Pnh, Pnl, (size_t)(cc + 1) * DD + r, v1);
                }
            }
        }
    }
}

// iteration 1 closed-form: P1 = 1.5 I - 0.5 S
__global__ void p1_kernel(const float* __restrict__ S, float* __restrict__ P,
                          __nv_bfloat16* __restrict__ Ph, __nv_bfloat16* __restrict__ Pl)
{
    const int i = blockIdx.x, j = threadIdx.x;
    const float v = ((i == j) ? 1.5f : 0.0f) - 0.5f * S[i * DD + j];
    P[i * DD + j] = v;
    split1(v, Ph[i * DD + j], Pl[i * DD + j]);
}

// ---------------------------------------------------------------------------
// Mean / trace / S / mc helpers
// ---------------------------------------------------------------------------
__global__ void mean_finalize(const float* __restrict__ colp, float* __restrict__ mean)
{
    const int j = blockIdx.x * 128 + threadIdx.x;
    float s = 0.0f;
#pragma unroll 8
    for (int r = 0; r < 512; r++)
        s += colp[(size_t)r * DD + j];
    mean[j] = s * (1.0f / (float)NROWS);
}

__global__ void trace_kernel(const float* __restrict__ G,
                             const float* __restrict__ mean,
                             float* __restrict__ scalars)
{
    __shared__ float sm[512];
    const int i = threadIdx.x;
    const float m = mean[i];
    sm[i] = G[i * DD + i] * (1.0f / (float)NROWS) - m * m + INV_TEMP;
    __syncthreads();
    for (int s = 256; s > 0; s >>= 1) {
        if (i < s) sm[i] += sm[i + s];
        __syncthreads();
    }
    if (i == 0) {
        const float tr = sm[0];
        scalars[0] = tr;
        scalars[1] = 1.0f / tr;
        scalars[2] = rsqrtf(tr);
    }
}

__global__ void s_kernel(const float* __restrict__ G,
                         const float* __restrict__ mean,
                         const float* __restrict__ scalars,
                         float* __restrict__ S,
                         __nv_bfloat16* __restrict__ Sh, __nv_bfloat16* __restrict__ Sl)
{
    const int i = blockIdx.x, j = threadIdx.x;
    const float invtr = scalars[1];
    float v = G[i * DD + j] * (1.0f / (float)NROWS) - mean[i] * mean[j];
    if (i == j) v += INV_TEMP;
    v *= invtr;
    S[i * DD + j] = v;
    split1(v, Sh[i * DD + j], Sl[i * DD + j]);
}

__global__ void mc_kernel(const float* __restrict__ mean, const float* __restrict__ P,
                          const float* __restrict__ scalars, float* __restrict__ mc)
{
    const int j = blockIdx.x * 128 + threadIdx.x;
    float s = 0.0f;
#pragma unroll 8
    for (int k = 0; k < DD; k++)
        s += mean[k] * P[(size_t)k * DD + j];
    mc[j] = s * scalars[2];
}

// ---------------------------------------------------------------------------
// Host orchestration
// ---------------------------------------------------------------------------
static void run_layer(const float* W, float* out)
{
    float *covp, *G, *S, *P, *Pn, *colp, *mean, *mc, *scal;
    __nv_bfloat16 *Ah, *Al, *Hh, *Hl, *Wh, *Wl, *Sh, *Sl;
    __nv_bfloat16 *Pah, *Pal, *Pbh, *Pbl, *T1h, *T1l, *T2h, *T2l;
    cudaGetSymbolAddress((void**)&covp, g_covp);
    cudaGetSymbolAddress((void**)&G,    g_G);
    cudaGetSymbolAddress((void**)&S,    g_S);
    cudaGetSymbolAddress((void**)&P,    g_P);
    cudaGetSymbolAddress((void**)&Pn,   g_Pn);
    cudaGetSymbolAddress((void**)&colp, g_colp);
    cudaGetSymbolAddress((void**)&mean, g_mean);
    cudaGetSymbolAddress((void**)&mc,   g_mc);
    cudaGetSymbolAddress((void**)&scal, g_scalars);
    cudaGetSymbolAddress((void**)&Ah,   g_Ah);
    cudaGetSymbolAddress((void**)&Al,   g_Al);
    cudaGetSymbolAddress((void**)&Hh,   g_Hh);
    cudaGetSymbolAddress((void**)&Hl,   g_Hl);
    cudaGetSymbolAddress((void**)&Wh,   g_Wh);
    cudaGetSymbolAddress((void**)&Wl,   g_Wl);
    cudaGetSymbolAddress((void**)&Sh,   g_Sh);
    cudaGetSymbolAddress((void**)&Sl,   g_Sl);
    cudaGetSymbolAddress((void**)&Pah,  g_Pah);
    cudaGetSymbolAddress((void**)&Pal,  g_Pal);
    cudaGetSymbolAddress((void**)&Pbh,  g_Pbh);
    cudaGetSymbolAddress((void**)&Pbl,  g_Pbl);
    cudaGetSymbolAddress((void**)&T1h,  g_T1h);
    cudaGetSymbolAddress((void**)&T1l,  g_T1l);
    cudaGetSymbolAddress((void**)&T2h,  g_T2h);
    cudaGetSymbolAddress((void**)&T2l,  g_T2l);

    const int wBlocks = (DD * DD) / (256 * 4);

    // H = in @ W  (epilogue writes Hh/Hl + column-sum partials)
    split_f32<<<wBlocks, 256>>>(W, Wh, Wl);
    hgemm<0><<<dim3(4, 512), 256, G1_SMEM>>>(Ah, Al, Wh, Wl,
                                             nullptr, Hh, Hl, nullptr, nullptr, colp);
    mean_finalize<<<4, 128>>>(colp, mean);

    // cov (upper-triangle tiles) -> G -> trace -> S (+split)
    hcov<<<dim3(10, 1, KSPLIT), 256, CV_SMEM>>>(Hh, Hl, covp);
    reduce_cov_sym<<<512, 512>>>(covp, G);
    trace_kernel<<<1, 512>>>(G, mean, scal);
    s_kernel<<<512, 512>>>(G, mean, scal, S, Sh, Sl);

    // Newton-Schulz: iteration 1 closed-form, 9 tensor-core iterations
    p1_kernel<<<512, 512>>>(S, P, Pah, Pal);
    float* Pf = P; float* Pg = Pn;
    __nv_bfloat16 *ah = Pah, *al = Pal, *bh = Pbh, *bl = Pbl;
    for (int t = 1; t < NS_ITERS; t++) {
        ns_pair<<<dim3(36, 1, 2), 128>>>(ah, al, Sh, Sl, T1h, T1l, T2h, T2l);
        ns_update<<<dim3(36), 128>>>(T2h, T2l, T1h, T1l, Pf, Pg, bh, bl);
        { float* t0 = Pf; Pf = Pg; Pg = t0; }
        { __nv_bfloat16* t1 = ah; ah = bh; bh = t1; }
        { __nv_bfloat16* t2 = al; al = bl; bl = t2; }
    }

    // out = (H @ P) * rsqrt(tr) - mc; splits of out -> Ah/Al (next layer input)
    mc_kernel<<<4, 128>>>(mean, Pf, scal, mc);
    hgemm<1><<<dim3(4, 512), 256, G1_SMEM>>>(Hh, Hl, ah, al,
                                             out, Ah, Al, scal, mc, nullptr);
}

extern "C" void kernel_launch(void* const* d_in, const int* in_sizes, int n_in,
                              void* d_out, int out_size)
{
    (void)in_sizes; (void)n_in; (void)out_size;
    const float* x  = (const float*)d_in[0];
    const float* W0 = (const float*)d_in[1];
    const float* W1 = (const float*)d_in[2];
    const float* W2 = (const float*)d_in[3];
    float* out = (float*)d_out;

    cudaFuncSetAttribute(hgemm<0>, cudaFuncAttributeMaxDynamicSharedMemorySize, G1_SMEM);
    cudaFuncSetAttribute(hgemm<1>, cudaFuncAttributeMaxDynamicSharedMemorySize, G1_SMEM);
    cudaFuncSetAttribute(hcov,     cudaFuncAttributeMaxDynamicSharedMemorySize, CV_SMEM);

    __nv_bfloat16 *Ah, *Al;
    cudaGetSymbolAddress((void**)&Ah, g_Ah);
    cudaGetSymbolAddress((void**)&Al, g_Al);

    split_f32<<<(NROWS * DD) / (256 * 4), 256>>>(x, Ah, Al);

    run_layer(W0, out);
    run_layer(W1, out + (size_t)NROWS * DD);
    run_layer(W2, out + (size_t)2 * NROWS * DD);
}